// round 7
// baseline (speedup 1.0000x reference)
#include <cuda_runtime.h>

#define HEIGHT  260
#define WIDTH   346
#define H_S     65
#define W_S     86
#define T_STEPS 64
#define BATCH   16
#define IMG     (H_S * W_S)      // 5590

// scratch (L2-resident working set ~46 MB)
__device__ float g_exc [T_STEPS * BATCH * IMG];   // exc, then overwritten with lgmd_in
__device__ float g_excr[T_STEPS * BATCH * IMG];   // row-passed (horizontal 7-tap) exc

// dynamic smem layout for k_exc
#define P_ELEMS  (2 * 67 * 88)                    // pooled + 1-halo
#define E_ELEMS  (65 * 92)                        // exc + 3-col zero borders
#define KEXC_SMEM ((P_ELEMS + E_ELEMS + 18) * 4)  // 71,232 B

// ---------------------------------------------------------------------------
// Kernel A: pool + 3x3 conv + ReLU + horizontal 7-tap. DRAM-bound (~780 MB).
// Separate smem buffers for p and e -> no register staging, 3 CTAs/SM.
// ---------------------------------------------------------------------------
__global__ void __launch_bounds__(512, 3)
k_exc(const float* __restrict__ x, const float* __restrict__ exc_w,
      const float* __restrict__ inh_w, float* __restrict__ out_dcmd) {
    const int tb = blockIdx.x;                       // t*BATCH + b
    const float* xb = x + (long long)tb * 2 * HEIGHT * WIDTH;

    extern __shared__ float smem[];
    float (*p)[67][88] = (float(*)[67][88])smem;
    float (*e)[92]     = (float(*)[92])(smem + P_ELEMS);
    float* w           = smem + P_ELEMS + E_ELEMS;

    const int tid = threadIdx.x;
    if (tid < 18) w[tid] = exc_w[tid];
    if (tid == 511) out_dcmd[tb] = 0.f;              // zero-init dcmd (poisoned)

    float u[7];
    {
        float cnorm = rsqrtf(-__ldg(&inh_w[3 * 7 + 3]));
        #pragma unroll
        for (int j = 0; j < 7; j++) u[j] = -__ldg(&inh_w[3 * 7 + j]) * cnorm;
    }

    // zero p halo border + e column borders
    for (int n = tid; n < 2 * 88; n += 512) {
        int c = n / 88, j = n % 88;
        p[c][0][j] = 0.f;  p[c][H_S + 1][j] = 0.f;
    }
    for (int n = tid; n < 2 * 67; n += 512) {
        int c = n / 67, i = n % 67;
        p[c][i][0] = 0.f;  p[c][i][W_S + 1] = 0.f;
    }
    for (int n = tid; n < H_S * 3; n += 512) {
        int i = n / 3, c = n % 3;
        e[i][c] = 0.f;  e[i][89 + c] = 0.f;
    }
    __syncthreads();

    // 4x4 avg pooling, vectorized loads (6 LDG per output)
    for (int n = tid; n < 2 * IMG; n += 512) {
        int c   = n / IMG;
        int rem = n - c * IMG;
        int i   = rem / W_S;
        int j   = rem - i * W_S;
        const float* src = xb + ((long long)c * HEIGHT + i * 4) * WIDTH + j * 4;
        float4 a  = *(const float4*)(src);
        float2 b0 = *(const float2*)(src + WIDTH);
        float2 b1 = *(const float2*)(src + WIDTH + 2);
        float4 c4 = *(const float4*)(src + 2 * WIDTH);
        float2 d0 = *(const float2*)(src + 3 * WIDTH);
        float2 d1 = *(const float2*)(src + 3 * WIDTH + 2);
        float s = a.x + a.y + a.z + a.w
                + b0.x + b0.y + b1.x + b1.y
                + c4.x + c4.y + c4.z + c4.w
                + d0.x + d0.y + d1.x + d1.y;
        p[c][i + 1][j + 1] = s * (1.f / 16.f);
    }
    __syncthreads();

    // 3x3 conv over 2 channels + relu -> e (separate buffer) and g_exc
    float* oexc = g_exc + (long long)tb * IMG;
    for (int n = tid; n < IMG; n += 512) {
        int i = n / W_S;
        int j = n - i * W_S;
        float acc = 0.f;
        #pragma unroll
        for (int c = 0; c < 2; c++)
            #pragma unroll
            for (int ky = 0; ky < 3; ky++)
                #pragma unroll
                for (int kx = 0; kx < 3; kx++)
                    acc += p[c][i + ky][j + kx] * w[c * 9 + ky * 3 + kx];
        acc = fmaxf(acc, 0.f);
        e[i][j + 3] = acc;
        oexc[n] = acc;
    }
    __syncthreads();

    // horizontal 7-tap -> g_excr
    float* oexcr = g_excr + (long long)tb * IMG;
    for (int n = tid; n < IMG; n += 512) {
        int i = n / W_S;
        int j = n - i * W_S;
        float a = 0.f;
        #pragma unroll
        for (int kx = 0; kx < 7; kx++) a += e[i][j + kx] * u[kx];
        oexcr[n] = a;
    }
}

// ---------------------------------------------------------------------------
// Kernel B: vertical 7-tap of g_excr[t-1], subtracted IN PLACE from g_exc[t].
// float2 throughout. t=0 is a no-op.
// ---------------------------------------------------------------------------
#define HROWS 33
#define W2    43
__global__ void k_inh(const float* __restrict__ inh_w) {
    const int tb = blockIdx.x;
    const int t  = tb / BATCH;
    if (t == 0) return;

    const int half  = blockIdx.y;
    const int row0  = half * HROWS;
    const int nrows = min(HROWS, H_S - row0);
    const int tid   = threadIdx.x;

    __shared__ float2 rp[HROWS + 6][W2];               // 39 x 43 float2

    float u[7];
    {
        float cnorm = rsqrtf(-__ldg(&inh_w[3 * 7 + 3]));
        #pragma unroll
        for (int j = 0; j < 7; j++) u[j] = -__ldg(&inh_w[3 * 7 + j]) * cnorm;
    }

    const float2* excr = (const float2*)(g_excr + (long long)(tb - BATCH) * IMG);
    const int loadrows = nrows + 6;

    for (int n = tid; n < loadrows * W2; n += 512) {
        int r  = n / W2;
        int c  = n - r * W2;
        int gr = row0 - 3 + r;
        rp[r][c] = (gr >= 0 && gr < H_S) ? __ldg(&excr[gr * W2 + c])
                                         : make_float2(0.f, 0.f);
    }
    __syncthreads();

    float2* g = (float2*)(g_exc + (long long)tb * IMG);
    for (int n = tid; n < nrows * W2; n += 512) {
        int r = n / W2;
        int c = n - r * W2;
        float cx = 0.f, cy = 0.f;
        #pragma unroll
        for (int k = 0; k < 7; k++) {
            float2 rv = rp[r + k][c];
            cx += rv.x * u[k];
            cy += rv.y * u[k];
        }
        int idx = (row0 + r) * W2 + c;
        float2 gv = g[idx];
        gv.x -= cx;  gv.y -= cy;
        g[idx] = gv;
    }
}

// ---------------------------------------------------------------------------
// Kernel C: pointwise membrane scan + fused dcmd reduction. 2 px/thread,
// depth-4 prefetch ring, barrier-free, one RED per warp per step.
// ---------------------------------------------------------------------------
#define SCT   128
#define IMG2  (IMG / 2)                    // 2795
#define SCB   ((IMG2 + SCT - 1) / SCT)     // 22

__global__ void k_scan(const float* __restrict__ dcmd_w,
                       float* __restrict__ out_dcmd,
                       float* __restrict__ out_spk) {
    const int b   = blockIdx.y;
    const int tid = threadIdx.x;
    const int p2  = blockIdx.x * SCT + tid;
    const bool act = p2 < IMG2;

    const long long base2   = (long long)b * IMG2 + p2;
    const long long stride2 = (long long)BATCH * IMG2;
    const float2* lg2 = (const float2*)g_exc;
    float2* out2 = (float2*)out_spk;

    float a0 = 0.f, a1 = 0.f;
    if (act) {
        float2 wv = __ldg(&((const float2*)dcmd_w)[p2]);
        a0 = fabsf(wv.x);  a1 = fabsf(wv.y);
    }

    float v0 = 0.f, v1 = 0.f;
    float2 ring[4];
    #pragma unroll
    for (int k = 0; k < 4; k++)
        ring[k] = act ? __ldg(&lg2[k * stride2 + base2]) : make_float2(0.f, 0.f);

    #pragma unroll
    for (int t = 0; t < T_STEPS; t++) {
        float2 lg = ring[t & 3];
        if (t + 4 < T_STEPS)
            ring[t & 3] = act ? __ldg(&lg2[(t + 4) * stride2 + base2])
                              : make_float2(0.f, 0.f);

        float vn0 = v0 + (lg.x - v0) * 0.5f;           // tau = 2 exact
        float vn1 = v1 + (lg.y - v1) * 0.5f;
        float sp0 = (vn0 >= 1.0f) ? 1.0f : 0.0f;
        float sp1 = (vn1 >= 1.0f) ? 1.0f : 0.0f;
        if (act) out2[t * stride2 + base2] = make_float2(sp0, sp1);
        v0 = vn0 * (1.0f - sp0);
        v1 = vn1 * (1.0f - sp1);

        float dsum = sp0 * a0 + sp1 * a1;
        #pragma unroll
        for (int off = 16; off; off >>= 1)
            dsum += __shfl_down_sync(0xffffffffu, dsum, off);
        if ((tid & 31) == 0 && dsum != 0.f)
            atomicAdd(&out_dcmd[t * BATCH + b], dsum);
    }
}

extern "C" void kernel_launch(void* const* d_in, const int* in_sizes, int n_in,
                              void* d_out, int out_size) {
    const float* x      = (const float*)d_in[0];
    const float* exc_w  = (const float*)d_in[1];
    const float* inh_w  = (const float*)d_in[2];
    const float* dcmd_w = (const float*)d_in[3];

    float* out      = (float*)d_out;
    float* out_dcmd = out;                         // (T,B)
    float* out_spk  = out + T_STEPS * BATCH;       // (T,B,1,H_S,W_S)

    cudaFuncSetAttribute(k_exc, cudaFuncAttributeMaxDynamicSharedMemorySize,
                         KEXC_SMEM);

    k_exc<<<T_STEPS * BATCH, 512, KEXC_SMEM>>>(x, exc_w, inh_w, out_dcmd);
    dim3 gi(T_STEPS * BATCH, 2);
    k_inh<<<gi, 512>>>(inh_w);
    dim3 gs(SCB, BATCH);
    k_scan<<<gs, SCT>>>(dcmd_w, out_dcmd, out_spk);
}

// round 8
// speedup vs baseline: 1.2438x; 1.2438x over previous
#include <cuda_runtime.h>

#define HEIGHT  260
#define WIDTH   346
#define H_S     65
#define W_S     86
#define T_STEPS 64
#define BATCH   16
#define IMG     (H_S * W_S)      // 5590

// scratch (L2-resident working set ~46 MB)
__device__ float g_exc [T_STEPS * BATCH * IMG];   // exc(t,b)
__device__ float g_lgmd[T_STEPS * BATCH * IMG];   // lgmd_in(t,b)

// ---------------------------------------------------------------------------
// Kernel A (R4 config — best measured: 132 µs, DRAM 72%):
// 4x4 avg pool (2 ch) + 2-ch 3x3 conv + ReLU. Static 47 KB smem, regs ~40.
// ---------------------------------------------------------------------------
__global__ void __launch_bounds__(512)
k_exc(const float* __restrict__ x, const float* __restrict__ exc_w,
      float* __restrict__ out_dcmd) {
    const int tb = blockIdx.x;                       // t*BATCH + b
    const float* xb = x + (long long)tb * 2 * HEIGHT * WIDTH;

    __shared__ float p[2][67][88];                   // pooled + 1-halo
    __shared__ float w[18];

    const int tid = threadIdx.x;
    if (tid < 18) w[tid] = exc_w[tid];
    if (tid == 511) out_dcmd[tb] = 0.f;              // zero-init dcmd (poisoned)

    // zero halo border of p
    for (int n = tid; n < 2 * 88; n += 512) {
        int c = n / 88, j = n % 88;
        p[c][0][j] = 0.f;  p[c][H_S + 1][j] = 0.f;
    }
    for (int n = tid; n < 2 * 67; n += 512) {
        int c = n / 67, i = n % 67;
        p[c][i][0] = 0.f;  p[c][i][W_S + 1] = 0.f;
    }
    __syncthreads();

    // 4x4 avg pooling, vectorized loads (6 LDG per output)
    for (int n = tid; n < 2 * IMG; n += 512) {
        int c   = n / IMG;
        int rem = n - c * IMG;
        int i   = rem / W_S;
        int j   = rem - i * W_S;
        const float* src = xb + ((long long)c * HEIGHT + i * 4) * WIDTH + j * 4;
        float4 a  = *(const float4*)(src);
        float2 b0 = *(const float2*)(src + WIDTH);
        float2 b1 = *(const float2*)(src + WIDTH + 2);
        float4 c4 = *(const float4*)(src + 2 * WIDTH);
        float2 d0 = *(const float2*)(src + 3 * WIDTH);
        float2 d1 = *(const float2*)(src + 3 * WIDTH + 2);
        float s = a.x + a.y + a.z + a.w
                + b0.x + b0.y + b1.x + b1.y
                + c4.x + c4.y + c4.z + c4.w
                + d0.x + d0.y + d1.x + d1.y;
        p[c][i + 1][j + 1] = s * (1.f / 16.f);
    }
    __syncthreads();

    // 3x3 conv over 2 channels + relu -> g_exc
    float* out = g_exc + (long long)tb * IMG;
    for (int n = tid; n < IMG; n += 512) {
        int i = n / W_S;
        int j = n - i * W_S;
        float acc = 0.f;
        #pragma unroll
        for (int c = 0; c < 2; c++)
            #pragma unroll
            for (int ky = 0; ky < 3; ky++)
                #pragma unroll
                for (int kx = 0; kx < 3; kx++)
                    acc += p[c][i + ky][j + kx] * w[c * 9 + ky * 3 + kx];
        out[n] = fmaxf(acc, 0.f);
    }
}

// ---------------------------------------------------------------------------
// Kernel B: lgmd_in[t] = exc[t] - sepconv7x7(exc[t-1]). Fully parallel over
// (t,b). Block = (tb, row-half). h-pass scalar from staged smem, v-pass
// float2. Writes g_lgmd (separate array: raw exc[t] still read by block t+1).
// ---------------------------------------------------------------------------
#define HROWS  33
#define IH     (HROWS + 6)          // 39
#define IW     (W_S + 6)            // 92
#define W2     43

__global__ void __launch_bounds__(512)
k_inh(const float* __restrict__ inh_w) {
    const int tb   = blockIdx.x;
    const int t    = tb / BATCH;
    const int half = blockIdx.y;
    const int row0 = half * HROWS;
    const int nrows = min(HROWS, H_S - row0);
    const int tid  = threadIdx.x;

    float* outp = g_lgmd + (long long)tb * IMG;
    const float* cur = g_exc + (long long)tb * IMG;

    if (t == 0) {  // zero-initialized inhibition buffer: lgmd_in[0] = exc[0]
        const float2* c2 = (const float2*)cur;
        float2* o2 = (float2*)outp;
        for (int n = row0 * W2 + tid; n < (row0 + nrows) * W2; n += 512)
            o2[n] = __ldg(&c2[n]);
        return;
    }

    __shared__ float raw[IH][IW];
    __shared__ float rp [IH][W_S + 2];

    float u[7];
    {
        float cnorm = rsqrtf(-__ldg(&inh_w[3 * 7 + 3]));
        #pragma unroll
        for (int j = 0; j < 7; j++) u[j] = -__ldg(&inh_w[3 * 7 + j]) * cnorm;
    }

    const float* prev = g_exc + (long long)(tb - BATCH) * IMG;  // t-1, same b
    const int loadrows = nrows + 6;

    // stage exc[t-1] strip with 3-halo, zero-padded
    for (int n = tid; n < loadrows * IW; n += 512) {
        int r  = n / IW;
        int c  = n - r * IW;
        int gr = row0 - 3 + r;
        int gc = c - 3;
        float val = 0.f;
        if (gr >= 0 && gr < H_S && gc >= 0 && gc < W_S)
            val = __ldg(&prev[gr * W_S + gc]);
        raw[r][c] = val;
    }
    __syncthreads();

    // horizontal 7-tap
    for (int n = tid; n < loadrows * W_S; n += 512) {
        int r = n / W_S;
        int c = n - r * W_S;
        float acc = 0.f;
        #pragma unroll
        for (int k = 0; k < 7; k++) acc += raw[r][c + k] * u[k];
        rp[r][c] = acc;
    }
    __syncthreads();

    // vertical 7-tap + subtract from exc[t], float2
    const float2* cur2 = (const float2*)cur;
    float2* out2 = (float2*)outp;
    float2 (*rp2)[W2 + 1] = (float2(*)[W2 + 1])rp;     // 88 floats = 44 float2/row
    for (int n = tid; n < nrows * W2; n += 512) {
        int r = n / W2;
        int c = n - r * W2;
        float cx = 0.f, cy = 0.f;
        #pragma unroll
        for (int k = 0; k < 7; k++) {
            float2 rv = rp2[r + k][c];
            cx += rv.x * u[k];
            cy += rv.y * u[k];
        }
        int idx = (row0 + r) * W2 + c;
        float2 ev = __ldg(&cur2[idx]);
        ev.x -= cx;  ev.y -= cy;
        out2[idx] = ev;
    }
}

// ---------------------------------------------------------------------------
// Kernel C: pointwise membrane scan + fused dcmd reduction. 2 px/thread,
// depth-4 prefetch ring, barrier-free, one RED per warp per step.
// ---------------------------------------------------------------------------
#define SCT   128
#define IMG2  (IMG / 2)                    // 2795
#define SCB   ((IMG2 + SCT - 1) / SCT)     // 22

__global__ void k_scan(const float* __restrict__ dcmd_w,
                       float* __restrict__ out_dcmd,
                       float* __restrict__ out_spk) {
    const int b   = blockIdx.y;
    const int tid = threadIdx.x;
    const int p2  = blockIdx.x * SCT + tid;
    const bool act = p2 < IMG2;

    const long long base2   = (long long)b * IMG2 + p2;
    const long long stride2 = (long long)BATCH * IMG2;
    const float2* lg2 = (const float2*)g_lgmd;
    float2* out2 = (float2*)out_spk;

    float a0 = 0.f, a1 = 0.f;
    if (act) {
        float2 wv = __ldg(&((const float2*)dcmd_w)[p2]);
        a0 = fabsf(wv.x);  a1 = fabsf(wv.y);
    }

    float v0 = 0.f, v1 = 0.f;
    float2 ring[4];
    #pragma unroll
    for (int k = 0; k < 4; k++)
        ring[k] = act ? __ldg(&lg2[k * stride2 + base2]) : make_float2(0.f, 0.f);

    #pragma unroll
    for (int t = 0; t < T_STEPS; t++) {
        float2 lg = ring[t & 3];
        if (t + 4 < T_STEPS)
            ring[t & 3] = act ? __ldg(&lg2[(t + 4) * stride2 + base2])
                              : make_float2(0.f, 0.f);

        float vn0 = v0 + (lg.x - v0) * 0.5f;           // tau = 2 exact
        float vn1 = v1 + (lg.y - v1) * 0.5f;
        float sp0 = (vn0 >= 1.0f) ? 1.0f : 0.0f;
        float sp1 = (vn1 >= 1.0f) ? 1.0f : 0.0f;
        if (act) out2[t * stride2 + base2] = make_float2(sp0, sp1);
        v0 = vn0 * (1.0f - sp0);
        v1 = vn1 * (1.0f - sp1);

        float dsum = sp0 * a0 + sp1 * a1;
        #pragma unroll
        for (int off = 16; off; off >>= 1)
            dsum += __shfl_down_sync(0xffffffffu, dsum, off);
        if ((tid & 31) == 0 && dsum != 0.f)
            atomicAdd(&out_dcmd[t * BATCH + b], dsum);
    }
}

extern "C" void kernel_launch(void* const* d_in, const int* in_sizes, int n_in,
                              void* d_out, int out_size) {
    const float* x      = (const float*)d_in[0];
    const float* exc_w  = (const float*)d_in[1];
    const float* inh_w  = (const float*)d_in[2];
    const float* dcmd_w = (const float*)d_in[3];

    float* out      = (float*)d_out;
    float* out_dcmd = out;                         // (T,B)
    float* out_spk  = out + T_STEPS * BATCH;       // (T,B,1,H_S,W_S)

    k_exc<<<T_STEPS * BATCH, 512>>>(x, exc_w, out_dcmd);
    dim3 gi(T_STEPS * BATCH, 2);
    k_inh<<<gi, 512>>>(inh_w);
    dim3 gs(SCB, BATCH);
    k_scan<<<gs, SCT>>>(dcmd_w, out_dcmd, out_spk);
}